// round 4
// baseline (speedup 1.0000x reference)
#include <cuda_runtime.h>
#include <math.h>

// Problem constants
#define TT 512
#define NB 64
#define DD 1024
#define HH 1024
#define TH 3072   // 3*H

#define KGN 4            // K-groups per block in step kernel
#define KPER (HH / KGN)  // 256

// Scratch for gi = x @ w_ih^T + b_ih : [T*N, 3H] fp32 = 402 MB
__device__ float g_gi[TT * NB * TH];

// ---------------------------------------------------------------------------
// Kernel 1: gi GEMM.  C[M=32768, N=3072] = A[M,1024] @ B[3072,1024]^T + bias
// ---------------------------------------------------------------------------
__global__ __launch_bounds__(256) void gi_gemm_kernel(
    const float* __restrict__ A,     // x  [32768, 1024]
    const float* __restrict__ B,     // w_ih [3072, 1024]
    const float* __restrict__ bias,  // b_ih [3072]
    float* __restrict__ C)           // gi [32768, 3072]
{
    __shared__ float As[16][132];
    __shared__ float Bs[16][132];

    const int tid = threadIdx.x;
    const int m0 = blockIdx.y * 128;
    const int n0 = blockIdx.x * 128;
    const int tx = tid & 15;
    const int ty = tid >> 4;
    const int lRow = tid >> 2;
    const int lK   = (tid & 3) * 4;

    float acc[8][8];
#pragma unroll
    for (int i = 0; i < 8; i++)
#pragma unroll
        for (int j = 0; j < 8; j++) acc[i][j] = 0.f;

    for (int k0 = 0; k0 < DD; k0 += 16) {
#pragma unroll
        for (int r = 0; r < 2; r++) {
            int mm = lRow + r * 64;
            float4 va = *(const float4*)&A[(size_t)(m0 + mm) * DD + k0 + lK];
            As[lK + 0][mm] = va.x; As[lK + 1][mm] = va.y;
            As[lK + 2][mm] = va.z; As[lK + 3][mm] = va.w;
            float4 vb = *(const float4*)&B[(size_t)(n0 + mm) * DD + k0 + lK];
            Bs[lK + 0][mm] = vb.x; Bs[lK + 1][mm] = vb.y;
            Bs[lK + 2][mm] = vb.z; Bs[lK + 3][mm] = vb.w;
        }
        __syncthreads();
#pragma unroll
        for (int k = 0; k < 16; k++) {
            float a[8], b[8];
            *(float4*)&a[0] = *(float4*)&As[k][ty * 4];
            *(float4*)&a[4] = *(float4*)&As[k][64 + ty * 4];
            *(float4*)&b[0] = *(float4*)&Bs[k][tx * 4];
            *(float4*)&b[4] = *(float4*)&Bs[k][64 + tx * 4];
#pragma unroll
            for (int i = 0; i < 8; i++)
#pragma unroll
                for (int j = 0; j < 8; j++)
                    acc[i][j] += a[i] * b[j];
        }
        __syncthreads();
    }

#pragma unroll
    for (int i = 0; i < 8; i++) {
        int m = m0 + ((i < 4) ? (ty * 4 + i) : (64 + ty * 4 + i - 4));
#pragma unroll
        for (int j = 0; j < 8; j++) {
            int n = n0 + ((j < 4) ? (tx * 4 + j) : (64 + tx * 4 + j - 4));
            C[(size_t)m * TH + n] = acc[i][j] + bias[n];
        }
    }
}

// ---------------------------------------------------------------------------
// Kernel 2: one GRU step — 512 threads = 4 K-groups x 128, occ 23%.
// grid = (64 j-tiles of 16, 2 n-halves of 32).
// Thread tile: 4n x 1j x 3 gates; K=256 per group; 3 partial buffers reduced
// by group 0, then thread-local gate fusion (no gh smem round-trip).
// Dynamic smem: Hs[4][32][36] | Ws[4][32][48] | red[3][128][13] | msk[32]
// ---------------------------------------------------------------------------
__device__ __forceinline__ float sigmoidf_(float x) {
    return 1.f / (1.f + expf(-x));
}

#define HS_ELEMS (KGN * 32 * 36)
#define WS_ELEMS (KGN * 32 * 48)
#define RED_ELEMS (3 * 128 * 13)
#define STEP_SMEM_FLOATS (HS_ELEMS + WS_ELEMS + RED_ELEMS + 32)
#define STEP_SMEM_BYTES (STEP_SMEM_FLOATS * 4)

__global__ __launch_bounds__(512) void gru_step_kernel(
    const float* __restrict__ gi_t,   // [64, 3072]
    const float* __restrict__ mask_t, // [64]
    const float* __restrict__ w_hh,   // [3072, 1024]
    const float* __restrict__ b_hh,   // [3072]
    const float* __restrict__ h_prev, // [64, 1024]
    float* __restrict__ h_out)        // [64, 1024]
{
    extern __shared__ __align__(16) float sm[];
    float* Hs  = sm;                    // [KGN][32][36] k-major, n minor
    float* Ws  = Hs + HS_ELEMS;         // [KGN][32][48] k-major, col minor
    float* red = Ws + WS_ELEMS;         // [3][128][13]
    float* msk = red + RED_ELEMS;       // [32]

    const int tid = threadIdx.x;
    const int kg  = tid >> 7;        // 0..3 K-group
    const int t   = tid & 127;
    const int tn  = t >> 4;          // 0..7 -> 4 n each
    const int tj  = t & 15;          // j within tile
    const int j0  = blockIdx.x * 16;
    const int n_base = blockIdx.y * 32;
    const int kbase0 = kg * KPER;

    float* HsK = Hs + kg * (32 * 36);
    float* WsK = Ws + kg * (32 * 48);

    if (tid < 32) msk[tid] = mask_t[n_base + tid];

    float accr[4], accz[4], accn[4];
#pragma unroll
    for (int i = 0; i < 4; i++) { accr[i] = 0.f; accz[i] = 0.f; accn[i] = 0.f; }

    __syncthreads();   // msk ready

    for (int kc = 0; kc < KPER; kc += 32) {
        const int kb = kbase0 + kc;

        // H tile: 32n x 32k = 256 float4 over 128 threads (2 each)
#pragma unroll
        for (int rep = 0; rep < 2; rep++) {
            int s  = t + rep * 128;
            int n  = s >> 3;            // 0..31
            int kq = (s & 7) * 4;       // 0,4,...,28
            float4 hv = *(const float4*)&h_prev[(n_base + n) * HH + kb + kq];
            float m = msk[n];
            HsK[(kq + 0) * 36 + n] = hv.x * m;
            HsK[(kq + 1) * 36 + n] = hv.y * m;
            HsK[(kq + 2) * 36 + n] = hv.z * m;
            HsK[(kq + 3) * 36 + n] = hv.w * m;
        }
        // W tile: 48 cols x 32k = 384 float4 over 128 threads (3 each)
#pragma unroll
        for (int rep = 0; rep < 3; rep++) {
            int s   = t + rep * 128;
            int col = s >> 3;           // 0..47
            int kq  = (s & 7) * 4;
            int g = col >> 4, jj = col & 15;
            float4 wv = *(const float4*)&w_hh[(size_t)(g * HH + j0 + jj) * HH + kb + kq];
            WsK[(kq + 0) * 48 + col] = wv.x;
            WsK[(kq + 1) * 48 + col] = wv.y;
            WsK[(kq + 2) * 48 + col] = wv.z;
            WsK[(kq + 3) * 48 + col] = wv.w;
        }
        __syncthreads();

#pragma unroll
        for (int k = 0; k < 32; k++) {
            float4 hv = *(const float4*)&HsK[k * 36 + tn * 4];
            float wr = WsK[k * 48 + tj];
            float wz = WsK[k * 48 + 16 + tj];
            float wn = WsK[k * 48 + 32 + tj];
            accr[0] += hv.x * wr; accr[1] += hv.y * wr;
            accr[2] += hv.z * wr; accr[3] += hv.w * wr;
            accz[0] += hv.x * wz; accz[1] += hv.y * wz;
            accz[2] += hv.z * wz; accz[3] += hv.w * wz;
            accn[0] += hv.x * wn; accn[1] += hv.y * wn;
            accn[2] += hv.z * wn; accn[3] += hv.w * wn;
        }
        __syncthreads();
    }

    // cross-group reduction: groups 1..3 publish partials
    if (kg > 0) {
        float* r = red + (size_t)(kg - 1) * (128 * 13) + t * 13;
#pragma unroll
        for (int i = 0; i < 4; i++) {
            r[i]     = accr[i];
            r[4 + i] = accz[i];
            r[8 + i] = accn[i];
        }
    }
    __syncthreads();

    if (kg == 0) {
        const int j = j0 + tj;
        const float br = b_hh[j];
        const float bz = b_hh[HH + j];
        const float bn = b_hh[2 * HH + j];
        const float* r0 = red + t * 13;
        const float* r1 = red + 128 * 13 + t * 13;
        const float* r2 = red + 2 * 128 * 13 + t * 13;
#pragma unroll
        for (int i = 0; i < 4; i++) {
            int nl = tn * 4 + i;
            int nglob = n_base + nl;
            float ghr = accr[i] + r0[i]     + r1[i]     + r2[i]     + br;
            float ghz = accz[i] + r0[4 + i] + r1[4 + i] + r2[4 + i] + bz;
            float ghn = accn[i] + r0[8 + i] + r1[8 + i] + r2[8 + i] + bn;
            const float* girow = gi_t + (size_t)nglob * TH;
            float gir = girow[j];
            float giz = girow[HH + j];
            float gin = girow[2 * HH + j];
            float hm  = h_prev[nglob * HH + j] * msk[nl];
            float r  = sigmoidf_(gir + ghr);
            float z  = sigmoidf_(giz + ghz);
            float nn = tanhf(gin + r * ghn);
            h_out[nglob * HH + j] = (1.f - z) * nn + z * hm;
        }
    }
}

// ---------------------------------------------------------------------------
extern "C" void kernel_launch(void* const* d_in, const int* in_sizes, int n_in,
                              void* d_out, int out_size)
{
    const float* x    = (const float*)d_in[0];
    const float* hx   = (const float*)d_in[1];
    const float* mask = (const float*)d_in[2];
    const float* w_ih = (const float*)d_in[3];
    const float* w_hh = (const float*)d_in[4];
    const float* b_ih = (const float*)d_in[5];
    const float* b_hh = (const float*)d_in[6];
    float* out = (float*)d_out;

    float* gi = nullptr;
    cudaGetSymbolAddress((void**)&gi, g_gi);

    // Allow >48KB dynamic smem for the step kernel (idempotent, capture-safe:
    // attribute set is not a stream operation).
    cudaFuncSetAttribute(gru_step_kernel,
                         cudaFuncAttributeMaxDynamicSharedMemorySize,
                         STEP_SMEM_BYTES);

    // Phase 1: bulk input projection
    dim3 gg(TH / 128, (TT * NB) / 128);   // (24, 256)
    gi_gemm_kernel<<<gg, 256>>>(x, w_ih, b_ih, gi);

    // Phase 2: sequential scan, one launch per timestep
    dim3 sg(HH / 16, 2);                  // (64, 2) = 128 blocks
    for (int tm = 0; tm < TT; tm++) {
        const float* hp = (tm == 0) ? hx : (out + (size_t)(tm - 1) * NB * HH);
        gru_step_kernel<<<sg, 512, STEP_SMEM_BYTES>>>(
            gi + (size_t)tm * NB * TH,
            mask + tm * NB,
            w_hh, b_hh,
            hp,
            out + (size_t)tm * NB * HH);
    }

    // h_final == out[T-1]
    cudaMemcpyAsync(out + (size_t)TT * NB * HH,
                    out + (size_t)(TT - 1) * NB * HH,
                    (size_t)NB * HH * sizeof(float),
                    cudaMemcpyDeviceToDevice, 0);
}